// round 1
// baseline (speedup 1.0000x reference)
#include <cuda_runtime.h>
#include <math.h>

#define TT 8192
#define DD 2048
#define RR 16
#define ALPHA_ 2.0f
#define NKEY 64

// ---------------- scratch (device globals: allocation-free) ----------------
__device__ float g_U [(size_t)TT*DD];
__device__ float g_G [(size_t)TT*DD];
__device__ float g_H [(size_t)TT*DD];
__device__ float g_DL[(size_t)TT*DD];
__device__ float g_P1[(size_t)TT*2*RR];
__device__ float g_P3[(size_t)TT*2*RR];
__device__ float g_cw[TT*2];
__device__ int   g_cnt[NKEY];
__device__ int   g_list[NKEY*TT];

// ---------------- zero the bucket counters (graph replays reuse state) -----
__global__ void zero_cnt_kernel() {
    if (threadIdx.x < NKEY) g_cnt[threadIdx.x] = 0;
}

// ---------------- router: logits, top-2, softmax, bucket by (e0,e1) -------
__global__ void router_kernel(const float* __restrict__ x,
                              const float* __restrict__ Wg)
{
    int w    = (blockIdx.x * blockDim.x + threadIdx.x) >> 5;
    int lane = threadIdx.x & 31;
    if (w >= TT) return;
    const float* xr = x + (size_t)w * DD;
    float a0=0.f,a1=0.f,a2=0.f,a3=0.f,a4=0.f,a5=0.f,a6=0.f,a7=0.f;
    for (int k = lane; k < DD; k += 32) {
        float xv = xr[k];
        a0 += xv * Wg[0*DD+k]; a1 += xv * Wg[1*DD+k];
        a2 += xv * Wg[2*DD+k]; a3 += xv * Wg[3*DD+k];
        a4 += xv * Wg[4*DD+k]; a5 += xv * Wg[5*DD+k];
        a6 += xv * Wg[6*DD+k]; a7 += xv * Wg[7*DD+k];
    }
    #pragma unroll
    for (int o = 16; o > 0; o >>= 1) {
        a0 += __shfl_xor_sync(0xffffffffu, a0, o);
        a1 += __shfl_xor_sync(0xffffffffu, a1, o);
        a2 += __shfl_xor_sync(0xffffffffu, a2, o);
        a3 += __shfl_xor_sync(0xffffffffu, a3, o);
        a4 += __shfl_xor_sync(0xffffffffu, a4, o);
        a5 += __shfl_xor_sync(0xffffffffu, a5, o);
        a6 += __shfl_xor_sync(0xffffffffu, a6, o);
        a7 += __shfl_xor_sync(0xffffffffu, a7, o);
    }
    if (lane == 0) {
        float v[8] = {a0,a1,a2,a3,a4,a5,a6,a7};
        int e0 = 0;
        #pragma unroll
        for (int e = 1; e < 8; e++) if (v[e] > v[e0]) e0 = e;
        int e1 = -1; float best = -3.0e38f;
        #pragma unroll
        for (int e = 0; e < 8; e++) if (e != e0 && v[e] > best) { best = v[e]; e1 = e; }
        // softmax over (v[e0], best), v[e0] is the max
        float ex = __expf(best - v[e0]);
        float c0 = 1.0f / (1.0f + ex);
        float c1 = ex * c0;
        g_cw[w*2+0] = c0;
        g_cw[w*2+1] = c1;
        int key = e0 * 8 + e1;
        int pos = atomicAdd(&g_cnt[key], 1);
        g_list[key*TT + pos] = w;
    }
}

// ---------------- fp32 SIMT GEMM: C = A[M,K] * B[N,K]^T (+ Csrc) ----------
template<int ADD>
__global__ void __launch_bounds__(256, 2)
sgemm_nt(const float* __restrict__ A, const float* __restrict__ B,
         const float* __restrict__ Csrc, float* __restrict__ C,
         int M, int N, int K)
{
    constexpr int BK = 8, LDSZ = 132;
    __shared__ float As[BK * LDSZ];
    __shared__ float Bs[BK * LDSZ];

    int tid = threadIdx.x;
    int bm = blockIdx.y * 128;
    int bn = blockIdx.x * 128;

    int lrow = tid >> 1;
    int lcol = (tid & 1) * 4;
    const float* Aptr = A + (size_t)(bm + lrow) * K + lcol;
    const float* Bptr = B + (size_t)(bn + lrow) * K + lcol;

    float4 pa = *(const float4*)Aptr;
    float4 pb = *(const float4*)Bptr;

    int tm = (tid >> 4) * 4;   // row fragment base (plus +64 for 2nd fragment)
    int tn = (tid & 15) * 4;   // col fragment base

    float acc[8][8];
    #pragma unroll
    for (int i = 0; i < 8; i++)
        #pragma unroll
        for (int j = 0; j < 8; j++) acc[i][j] = 0.0f;

    for (int kt = 0; kt < K; kt += BK) {
        As[(lcol+0)*LDSZ + lrow] = pa.x;
        As[(lcol+1)*LDSZ + lrow] = pa.y;
        As[(lcol+2)*LDSZ + lrow] = pa.z;
        As[(lcol+3)*LDSZ + lrow] = pa.w;
        Bs[(lcol+0)*LDSZ + lrow] = pb.x;
        Bs[(lcol+1)*LDSZ + lrow] = pb.y;
        Bs[(lcol+2)*LDSZ + lrow] = pb.z;
        Bs[(lcol+3)*LDSZ + lrow] = pb.w;
        __syncthreads();

        if (kt + BK < K) {
            pa = *(const float4*)(Aptr + kt + BK);
            pb = *(const float4*)(Bptr + kt + BK);
        }

        #pragma unroll
        for (int k = 0; k < BK; k++) {
            float4 ra0 = *(const float4*)&As[k*LDSZ + tm];
            float4 ra1 = *(const float4*)&As[k*LDSZ + tm + 64];
            float4 rb0 = *(const float4*)&Bs[k*LDSZ + tn];
            float4 rb1 = *(const float4*)&Bs[k*LDSZ + tn + 64];
            float ra[8] = {ra0.x, ra0.y, ra0.z, ra0.w, ra1.x, ra1.y, ra1.z, ra1.w};
            float rb[8] = {rb0.x, rb0.y, rb0.z, rb0.w, rb1.x, rb1.y, rb1.z, rb1.w};
            #pragma unroll
            for (int i = 0; i < 8; i++)
                #pragma unroll
                for (int j = 0; j < 8; j++)
                    acc[i][j] += ra[i] * rb[j];
        }
        __syncthreads();
    }

    #pragma unroll
    for (int i = 0; i < 8; i++) {
        int m = bm + tm + ((i < 4) ? i : (60 + i));
        float* crow = C + (size_t)m * N + bn;
        if (ADD) {
            const float* srow = Csrc + (size_t)m * N + bn;
            float4 s0 = *(const float4*)(srow + tn);
            float4 s1 = *(const float4*)(srow + tn + 64);
            float4 v0 = make_float4(acc[i][0]+s0.x, acc[i][1]+s0.y, acc[i][2]+s0.z, acc[i][3]+s0.w);
            float4 v1 = make_float4(acc[i][4]+s1.x, acc[i][5]+s1.y, acc[i][6]+s1.z, acc[i][7]+s1.w);
            *(float4*)(crow + tn)      = v0;
            *(float4*)(crow + tn + 64) = v1;
        } else {
            *(float4*)(crow + tn)      = make_float4(acc[i][0], acc[i][1], acc[i][2], acc[i][3]);
            *(float4*)(crow + tn + 64) = make_float4(acc[i][4], acc[i][5], acc[i][6], acc[i][7]);
        }
    }
}

// ---------------- grouped LoRA-in: P1/P3 = x @ B1[e]^T, x @ B3[e]^T -------
// grid (256 chunks, 64 keys); block = 32 tokens sharing the same (e0,e1)
__global__ void __launch_bounds__(256)
lora_in_kernel(const float* __restrict__ x,
               const float* __restrict__ B1, const float* __restrict__ B3)
{
    int key   = blockIdx.y;
    int chunk = blockIdx.x;
    int cnt   = g_cnt[key];
    if (chunk * 32 >= cnt) return;
    int e0 = key >> 3, e1 = key & 7;

    __shared__ int   stok[32];
    __shared__ float sx[32][65];
    __shared__ float sB[4][16][65];   // 0:B1@e0 1:B1@e1 2:B3@e0 3:B3@e1

    int tid = threadIdx.x;
    if (tid < 32) {
        int it = chunk * 32 + tid;
        stok[tid] = (it < cnt) ? g_list[key*TT + it] : -1;
    }
    __syncthreads();

    int ltok = tid >> 3;
    int j    = tid & 7;
    int t    = stok[ltok];

    float acc1[4] = {0,0,0,0};
    float acc3[4] = {0,0,0,0};

    for (int kb = 0; kb < DD; kb += 64) {
        {   // x tile: 32 rows x 64 cols; 8 threads/row, 8 floats each
            int row = tid >> 3, cg = (tid & 7) * 8;
            int tok = stok[row];
            if (tok >= 0) {
                const float* src = x + (size_t)tok * DD + kb + cg;
                float4 v0 = *(const float4*)src;
                float4 v1 = *(const float4*)(src + 4);
                sx[row][cg+0]=v0.x; sx[row][cg+1]=v0.y; sx[row][cg+2]=v0.z; sx[row][cg+3]=v0.w;
                sx[row][cg+4]=v1.x; sx[row][cg+5]=v1.y; sx[row][cg+6]=v1.z; sx[row][cg+7]=v1.w;
            } else {
                #pragma unroll
                for (int q = 0; q < 8; q++) sx[row][cg+q] = 0.0f;
            }
        }
        {   // B slices: 4 x 16 x 64
            int s  = tid >> 6;
            int rr = (tid & 63) >> 2;
            int cg = (tid & 3) * 16;
            int e  = (s & 1) ? e1 : e0;
            const float* M = ((s < 2) ? B1 : B3) + ((size_t)e * RR + rr) * DD + kb + cg;
            #pragma unroll
            for (int q = 0; q < 16; q += 4) {
                float4 v = *(const float4*)(M + q);
                sB[s][rr][cg+q+0]=v.x; sB[s][rr][cg+q+1]=v.y;
                sB[s][rr][cg+q+2]=v.z; sB[s][rr][cg+q+3]=v.w;
            }
        }
        __syncthreads();

        #pragma unroll 4
        for (int kk = 0; kk < 64; kk++) {
            float xv = sx[ltok][kk];
            #pragma unroll
            for (int cc = 0; cc < 4; cc++) {
                int c = j*4 + cc;
                int slot = c >> 4, r = c & 15;
                acc1[cc] += xv * sB[slot][r][kk];
                acc3[cc] += xv * sB[2+slot][r][kk];
            }
        }
        __syncthreads();
    }

    if (t >= 0) {
        #pragma unroll
        for (int cc = 0; cc < 4; cc++) {
            int c = j*4 + cc;
            int slot = c >> 4, r = c & 15;
            g_P1[((size_t)t*2 + slot)*RR + r] = acc1[cc];
            g_P3[((size_t)t*2 + slot)*RR + r] = acc3[cc];
        }
    }
}

// ---------------- grouped middle: deltas + SiLU + hbar + P2 + Dlow --------
// grid (256 chunks, 64 keys); block = 32 tokens x 64-wide d-chunks
__global__ void __launch_bounds__(256)
middle_kernel(const float* __restrict__ A1, const float* __restrict__ A3,
              const float* __restrict__ B2, const float* __restrict__ A2)
{
    int key   = blockIdx.y;
    int chunk = blockIdx.x;
    int cnt   = g_cnt[key];
    if (chunk * 32 >= cnt) return;
    int e0 = key >> 3, e1 = key & 7;

    __shared__ int   stok[32];
    __shared__ float scw[32][2];
    __shared__ float sP1[32][2][17];
    __shared__ float sP3[32][2][17];
    __shared__ float sP2[32][2][17];
    __shared__ float sM[6][64*20];   // 0:A1e0 1:A1e1 2:A3e0 3:A3e1 4:B2e0(T) 5:B2e1(T)

    int tid = threadIdx.x;
    if (tid < 32) {
        int it = chunk * 32 + tid;
        stok[tid] = (it < cnt) ? g_list[key*TT + it] : -1;
    }
    __syncthreads();
    if (tid < 64) {
        int lt = tid >> 1, slot = tid & 1;
        int t = stok[lt];
        scw[lt][slot] = (t >= 0) ? g_cw[t*2 + slot] : 0.0f;
    }
    for (int idx = tid; idx < 1024; idx += 256) {
        int lt = idx >> 5, slot = (idx >> 4) & 1, r = idx & 15;
        int t = stok[lt];
        sP1[lt][slot][r] = (t >= 0) ? g_P1[((size_t)t*2 + slot)*RR + r] : 0.0f;
        sP3[lt][slot][r] = (t >= 0) ? g_P3[((size_t)t*2 + slot)*RR + r] : 0.0f;
    }
    __syncthreads();

    int ltok = tid >> 3;
    int j    = tid & 7;
    int t    = stok[ltok];
    float c0 = scw[ltok][0], c1 = scw[ltok][1];

    float p2a[16], p2b[16];
    #pragma unroll
    for (int r = 0; r < 16; r++) { p2a[r] = 0.0f; p2b[r] = 0.0f; }

    // ---- phase 1: h, hbar, P2 partials ----
    for (int db = 0; db < DD; db += 64) {
        // A-type slices (contiguous [d][r])
        {
            const float* s0 = A1 + ((size_t)e0*DD + db)*RR;
            const float* s1 = A1 + ((size_t)e1*DD + db)*RR;
            const float* s2 = A3 + ((size_t)e0*DD + db)*RR;
            const float* s3 = A3 + ((size_t)e1*DD + db)*RR;
            for (int idx = tid; idx < 1024; idx += 256) {
                int dd = idx >> 4, r = idx & 15;
                int o = dd*20 + r;
                sM[0][o] = s0[idx]; sM[1][o] = s1[idx];
                sM[2][o] = s2[idx]; sM[3][o] = s3[idx];
            }
            const float* b0 = B2 + (size_t)e0*RR*DD + db;
            const float* b1p = B2 + (size_t)e1*RR*DD + db;
            for (int idx = tid; idx < 1024; idx += 256) {
                int r = idx >> 6, dd = idx & 63;
                sM[4][dd*20 + r] = b0[(size_t)r*DD + dd];
                sM[5][dd*20 + r] = b1p[(size_t)r*DD + dd];
            }
        }
        __syncthreads();

        #pragma unroll
        for (int i = 0; i < 8; i++) {
            int dd = j + 8*i;
            int d  = db + dd;
            float u = 0.0f, g = 0.0f;
            if (t >= 0) {
                u = g_U[(size_t)t*DD + d];
                g = g_G[(size_t)t*DD + d];
            }
            const float* a1p = &sM[0][dd*20];
            const float* a1q = &sM[1][dd*20];
            const float* a3p = &sM[2][dd*20];
            const float* a3q = &sM[3][dd*20];

            float d1a = 0.f, d3a = 0.f, d1b = 0.f, d3b = 0.f;
            #pragma unroll
            for (int r = 0; r < 16; r++) {
                d1a += sP1[ltok][0][r] * a1p[r];
                d3a += sP3[ltok][0][r] * a3p[r];
                d1b += sP1[ltok][1][r] * a1q[r];
                d3b += sP3[ltok][1][r] * a3q[r];
            }
            float h1a = u + ALPHA_*d1a, h3a = g + ALPHA_*d3a;
            float h1b = u + ALPHA_*d1b, h3b = g + ALPHA_*d3b;
            float hA = (h1a / (1.0f + __expf(-h1a))) * h3a;
            float hB = (h1b / (1.0f + __expf(-h1b))) * h3b;
            if (t < 0) { hA = 0.0f; hB = 0.0f; }

            if (t >= 0)
                g_H[(size_t)t*DD + d] = c0*hA + c1*hB;

            const float* b2a = &sM[4][dd*20];
            const float* b2b = &sM[5][dd*20];
            #pragma unroll
            for (int r = 0; r < 16; r++) {
                p2a[r] += hA * b2a[r];
                p2b[r] += hB * b2b[r];
            }
        }
        __syncthreads();
    }

    // reduce P2 partials across the 8 lanes of each token group
    #pragma unroll
    for (int r = 0; r < 16; r++) {
        #pragma unroll
        for (int o = 4; o > 0; o >>= 1) {
            p2a[r] += __shfl_down_sync(0xffffffffu, p2a[r], o);
            p2b[r] += __shfl_down_sync(0xffffffffu, p2b[r], o);
        }
    }
    if (j == 0) {
        #pragma unroll
        for (int r = 0; r < 16; r++) {
            sP2[ltok][0][r] = p2a[r];
            sP2[ltok][1][r] = p2b[r];
        }
    }
    __syncthreads();

    // ---- phase 2: Dlow = alpha * (c0*P2a@A2[e0]^T + c1*P2b@A2[e1]^T) ----
    for (int db = 0; db < DD; db += 64) {
        {
            const float* s0 = A2 + ((size_t)e0*DD + db)*RR;
            const float* s1 = A2 + ((size_t)e1*DD + db)*RR;
            for (int idx = tid; idx < 1024; idx += 256) {
                int dd = idx >> 4, r = idx & 15;
                int o = dd*20 + r;
                sM[0][o] = s0[idx];
                sM[1][o] = s1[idx];
            }
        }
        __syncthreads();
        if (t >= 0) {
            #pragma unroll
            for (int i = 0; i < 8; i++) {
                int dd = j + 8*i;
                int d  = db + dd;
                const float* a2p = &sM[0][dd*20];
                const float* a2q = &sM[1][dd*20];
                float s0 = 0.f, s1 = 0.f;
                #pragma unroll
                for (int r = 0; r < 16; r++) {
                    s0 += sP2[ltok][0][r] * a2p[r];
                    s1 += sP2[ltok][1][r] * a2q[r];
                }
                g_DL[(size_t)t*DD + d] = ALPHA_ * (c0*s0 + c1*s1);
            }
        }
        __syncthreads();
    }
}

// ---------------- host launch ---------------------------------------------
extern "C" void kernel_launch(void* const* d_in, const int* in_sizes, int n_in,
                              void* d_out, int out_size)
{
    const float* x     = (const float*)d_in[0];
    const float* Wg    = (const float*)d_in[1];
    const float* Wup   = (const float*)d_in[2];
    const float* Wgate = (const float*)d_in[3];
    const float* Wdown = (const float*)d_in[4];
    const float* A1    = (const float*)d_in[5];
    const float* B1    = (const float*)d_in[6];
    const float* A2    = (const float*)d_in[7];
    const float* B2    = (const float*)d_in[8];
    const float* A3    = (const float*)d_in[9];
    const float* B3    = (const float*)d_in[10];
    float* out = (float*)d_out;

    float *U, *G, *H, *DL;
    cudaGetSymbolAddress((void**)&U,  g_U);
    cudaGetSymbolAddress((void**)&G,  g_G);
    cudaGetSymbolAddress((void**)&H,  g_H);
    cudaGetSymbolAddress((void**)&DL, g_DL);

    zero_cnt_kernel<<<1, 64>>>();
    router_kernel<<<TT/8, 256>>>(x, Wg);

    dim3 ggrid(DD/128, TT/128);
    sgemm_nt<0><<<ggrid, 256>>>(x, Wup,   nullptr, U, TT, DD, DD);
    sgemm_nt<0><<<ggrid, 256>>>(x, Wgate, nullptr, G, TT, DD, DD);

    lora_in_kernel<<<dim3(256, NKEY), 256>>>(x, B1, B3);
    middle_kernel <<<dim3(256, NKEY), 256>>>(A1, A3, B2, A2);

    sgemm_nt<1><<<ggrid, 256>>>(H, Wdown, DL, out, TT, DD, DD);
}

// round 4
// speedup vs baseline: 1.2418x; 1.2418x over previous
#include <cuda_runtime.h>
#include <cuda_bf16.h>
#include <stdint.h>
#include <cstdint>
#include <math.h>

#define TT 8192
#define DD 2048
#define RR 16
#define ALPHA_ 2.0f
#define NKEY 64

// ---------------- scratch (device globals: allocation-free) ----------------
__device__ float g_U [(size_t)TT*DD];
__device__ float g_G [(size_t)TT*DD];
__device__ float g_H [(size_t)TT*DD];
__device__ float g_DL[(size_t)TT*DD];
__device__ float g_P1[(size_t)TT*2*RR];
__device__ float g_P3[(size_t)TT*2*RR];
__device__ float g_cw[TT*2];
__device__ int   g_cnt[NKEY];
__device__ int   g_list[NKEY*TT];

// ---------------- zero the bucket counters (graph replays reuse state) -----
__global__ void zero_cnt_kernel() {
    if (threadIdx.x < NKEY) g_cnt[threadIdx.x] = 0;
}

// ---------------- router: logits, top-2, softmax, bucket by (e0,e1) -------
__global__ void router_kernel(const float* __restrict__ x,
                              const float* __restrict__ Wg)
{
    int w    = (blockIdx.x * blockDim.x + threadIdx.x) >> 5;
    int lane = threadIdx.x & 31;
    if (w >= TT) return;
    const float* xr = x + (size_t)w * DD;
    float a0=0.f,a1=0.f,a2=0.f,a3=0.f,a4=0.f,a5=0.f,a6=0.f,a7=0.f;
    for (int k = lane; k < DD; k += 32) {
        float xv = xr[k];
        a0 += xv * Wg[0*DD+k]; a1 += xv * Wg[1*DD+k];
        a2 += xv * Wg[2*DD+k]; a3 += xv * Wg[3*DD+k];
        a4 += xv * Wg[4*DD+k]; a5 += xv * Wg[5*DD+k];
        a6 += xv * Wg[6*DD+k]; a7 += xv * Wg[7*DD+k];
    }
    #pragma unroll
    for (int o = 16; o > 0; o >>= 1) {
        a0 += __shfl_xor_sync(0xffffffffu, a0, o);
        a1 += __shfl_xor_sync(0xffffffffu, a1, o);
        a2 += __shfl_xor_sync(0xffffffffu, a2, o);
        a3 += __shfl_xor_sync(0xffffffffu, a3, o);
        a4 += __shfl_xor_sync(0xffffffffu, a4, o);
        a5 += __shfl_xor_sync(0xffffffffu, a5, o);
        a6 += __shfl_xor_sync(0xffffffffu, a6, o);
        a7 += __shfl_xor_sync(0xffffffffu, a7, o);
    }
    if (lane == 0) {
        float v[8] = {a0,a1,a2,a3,a4,a5,a6,a7};
        int e0 = 0;
        #pragma unroll
        for (int e = 1; e < 8; e++) if (v[e] > v[e0]) e0 = e;
        int e1 = -1; float best = -3.0e38f;
        #pragma unroll
        for (int e = 0; e < 8; e++) if (e != e0 && v[e] > best) { best = v[e]; e1 = e; }
        float ex = __expf(best - v[e0]);
        float c0 = 1.0f / (1.0f + ex);
        float c1 = ex * c0;
        g_cw[w*2+0] = c0;
        g_cw[w*2+1] = c1;
        int key = e0 * 8 + e1;
        int pos = atomicAdd(&g_cnt[key], 1);
        g_list[key*TT + pos] = w;
    }
}

// ---------------- bf16x3 tensor-core GEMM: C = A[M,K]*B[N,K]^T (+Csrc) ----
// Split a = ah + al (bf16 hi + bf16 residual); compute ah*bh + ah*bl + al*bh
// with fp32 accumulation -> ~1e-5 relative error at 3x bf16 mma cost.
#define MMA16816(dreg, Ra0, Ra1, Ra2, Ra3, Rb0, Rb1)                          \
    asm volatile(                                                             \
        "mma.sync.aligned.m16n8k16.row.col.f32.bf16.bf16.f32 "                \
        "{%0,%1,%2,%3},{%4,%5,%6,%7},{%8,%9},{%0,%1,%2,%3};"                  \
        : "+f"((dreg)[0]), "+f"((dreg)[1]), "+f"((dreg)[2]), "+f"((dreg)[3])  \
        : "r"(Ra0), "r"(Ra1), "r"(Ra2), "r"(Ra3), "r"(Rb0), "r"(Rb1))

__device__ __forceinline__ void split2(unsigned int* Sh, unsigned int* Sl, int w,
                                       float X, float Y)
{
    float hx = __bfloat162float(__float2bfloat16_rn(X));
    float hy = __bfloat162float(__float2bfloat16_rn(Y));
    __nv_bfloat162 hv = __floats2bfloat162_rn(X, Y);
    __nv_bfloat162 lv = __floats2bfloat162_rn(X - hx, Y - hy);
    Sh[w] = *(unsigned int*)&hv;
    Sl[w] = *(unsigned int*)&lv;
}

template<int ADD>
__global__ void __launch_bounds__(512)
gemm_bf16x3(const float* __restrict__ A, const float* __restrict__ B,
            const float* __restrict__ Csrc, float* __restrict__ C,
            int M, int N, int K)
{
    constexpr int PW = 20;   // words (bf16x2) per row: 16 data + 4 pad
    __shared__ unsigned int sAh[128*PW], sAl[128*PW];
    __shared__ unsigned int sBh[128*PW], sBl[128*PW];

    int tid  = threadIdx.x;
    int lane = tid & 31, warp = tid >> 5;
    int g  = lane >> 2, t4 = lane & 3;
    int wm = warp >> 2, wn = warp & 3;
    int bm = blockIdx.y * 128, bn = blockIdx.x * 128;

    // global staging: thread -> row lr, k-chunk lk (8 floats = 2 float4)
    int lr = tid >> 2, lk = (tid & 3) * 8;
    const float* Ap = A + (size_t)(bm + lr) * K + lk;
    const float* Bp = B + (size_t)(bn + lr) * K + lk;

    float4 pa0 = *(const float4*)Ap, pa1 = *(const float4*)(Ap + 4);
    float4 pb0 = *(const float4*)Bp, pb1 = *(const float4*)(Bp + 4);

    float acc[2][4][4];
    #pragma unroll
    for (int i = 0; i < 2; i++)
        #pragma unroll
        for (int j = 0; j < 4; j++)
            #pragma unroll
            for (int q = 0; q < 4; q++) acc[i][j][q] = 0.0f;

    int wbase = lr * PW + (tid & 3) * 4;

    for (int kt = 0; kt < K; kt += 32) {
        split2(sAh, sAl, wbase + 0, pa0.x, pa0.y);
        split2(sAh, sAl, wbase + 1, pa0.z, pa0.w);
        split2(sAh, sAl, wbase + 2, pa1.x, pa1.y);
        split2(sAh, sAl, wbase + 3, pa1.z, pa1.w);
        split2(sBh, sBl, wbase + 0, pb0.x, pb0.y);
        split2(sBh, sBl, wbase + 1, pb0.z, pb0.w);
        split2(sBh, sBl, wbase + 2, pb1.x, pb1.y);
        split2(sBh, sBl, wbase + 3, pb1.z, pb1.w);
        __syncthreads();

        if (kt + 32 < K) {
            pa0 = *(const float4*)(Ap + kt + 32);
            pa1 = *(const float4*)(Ap + kt + 36);
            pb0 = *(const float4*)(Bp + kt + 32);
            pb1 = *(const float4*)(Bp + kt + 36);
        }

        #pragma unroll
        for (int ks = 0; ks < 2; ks++) {
            int kw = ks * 8;
            unsigned int bh[4][2], bl[4][2], af[2][4];
            #pragma unroll
            for (int nt = 0; nt < 4; nt++) {
                int o = (wn*32 + nt*8 + g) * PW + kw + t4;
                bh[nt][0] = sBh[o]; bh[nt][1] = sBh[o + 4];
                bl[nt][0] = sBl[o]; bl[nt][1] = sBl[o + 4];
            }
            #pragma unroll
            for (int mt = 0; mt < 2; mt++) {
                int o = (wm*32 + mt*16 + g) * PW + kw + t4;
                af[mt][0] = sAh[o];           af[mt][1] = sAh[o + 8*PW];
                af[mt][2] = sAh[o + 4];       af[mt][3] = sAh[o + 8*PW + 4];
            }
            #pragma unroll
            for (int mt = 0; mt < 2; mt++)
                #pragma unroll
                for (int nt = 0; nt < 4; nt++)
                    MMA16816(acc[mt][nt], af[mt][0], af[mt][1], af[mt][2], af[mt][3],
                             bh[nt][0], bh[nt][1]);
            #pragma unroll
            for (int mt = 0; mt < 2; mt++)
                #pragma unroll
                for (int nt = 0; nt < 4; nt++)
                    MMA16816(acc[mt][nt], af[mt][0], af[mt][1], af[mt][2], af[mt][3],
                             bl[nt][0], bl[nt][1]);
            #pragma unroll
            for (int mt = 0; mt < 2; mt++) {
                int o = (wm*32 + mt*16 + g) * PW + kw + t4;
                af[mt][0] = sAl[o];           af[mt][1] = sAl[o + 8*PW];
                af[mt][2] = sAl[o + 4];       af[mt][3] = sAl[o + 8*PW + 4];
            }
            #pragma unroll
            for (int mt = 0; mt < 2; mt++)
                #pragma unroll
                for (int nt = 0; nt < 4; nt++)
                    MMA16816(acc[mt][nt], af[mt][0], af[mt][1], af[mt][2], af[mt][3],
                             bh[nt][0], bh[nt][1]);
        }
        __syncthreads();
    }

    // epilogue
    #pragma unroll
    for (int mt = 0; mt < 2; mt++) {
        int r0 = bm + wm*32 + mt*16 + g;
        #pragma unroll
        for (int nt = 0; nt < 4; nt++) {
            int c0 = bn + wn*32 + nt*8 + t4*2;
            float2 v0 = make_float2(acc[mt][nt][0], acc[mt][nt][1]);
            float2 v1 = make_float2(acc[mt][nt][2], acc[mt][nt][3]);
            if (ADD) {
                float2 s0 = *(const float2*)(Csrc + (size_t)r0 * N + c0);
                float2 s1 = *(const float2*)(Csrc + (size_t)(r0+8) * N + c0);
                v0.x += s0.x; v0.y += s0.y;
                v1.x += s1.x; v1.y += s1.y;
            }
            *(float2*)(C + (size_t)r0     * N + c0) = v0;
            *(float2*)(C + (size_t)(r0+8) * N + c0) = v1;
        }
    }
}

// ---------------- grouped LoRA-in: P1/P3 = x @ B1[e]^T, x @ B3[e]^T -------
__global__ void __launch_bounds__(256)
lora_in_kernel(const float* __restrict__ x,
               const float* __restrict__ B1, const float* __restrict__ B3)
{
    int key   = blockIdx.y;
    int chunk = blockIdx.x;
    int cnt   = g_cnt[key];
    if (chunk * 32 >= cnt) return;
    int e0 = key >> 3, e1 = key & 7;

    __shared__ int   stok[32];
    __shared__ float sx[32][65];
    __shared__ float sB[4][16][65];

    int tid = threadIdx.x;
    if (tid < 32) {
        int it = chunk * 32 + tid;
        stok[tid] = (it < cnt) ? g_list[key*TT + it] : -1;
    }
    __syncthreads();

    int ltok = tid >> 3;
    int j    = tid & 7;
    int t    = stok[ltok];

    float acc1[4] = {0,0,0,0};
    float acc3[4] = {0,0,0,0};

    for (int kb = 0; kb < DD; kb += 64) {
        {
            int row = tid >> 3, cg = (tid & 7) * 8;
            int tok = stok[row];
            if (tok >= 0) {
                const float* src = x + (size_t)tok * DD + kb + cg;
                float4 v0 = *(const float4*)src;
                float4 v1 = *(const float4*)(src + 4);
                sx[row][cg+0]=v0.x; sx[row][cg+1]=v0.y; sx[row][cg+2]=v0.z; sx[row][cg+3]=v0.w;
                sx[row][cg+4]=v1.x; sx[row][cg+5]=v1.y; sx[row][cg+6]=v1.z; sx[row][cg+7]=v1.w;
            } else {
                #pragma unroll
                for (int q = 0; q < 8; q++) sx[row][cg+q] = 0.0f;
            }
        }
        {
            int s  = tid >> 6;
            int rr = (tid & 63) >> 2;
            int cg = (tid & 3) * 16;
            int e  = (s & 1) ? e1 : e0;
            const float* M = ((s < 2) ? B1 : B3) + ((size_t)e * RR + rr) * DD + kb + cg;
            #pragma unroll
            for (int q = 0; q < 16; q += 4) {
                float4 v = *(const float4*)(M + q);
                sB[s][rr][cg+q+0]=v.x; sB[s][rr][cg+q+1]=v.y;
                sB[s][rr][cg+q+2]=v.z; sB[s][rr][cg+q+3]=v.w;
            }
        }
        __syncthreads();

        #pragma unroll 4
        for (int kk = 0; kk < 64; kk++) {
            float xv = sx[ltok][kk];
            #pragma unroll
            for (int cc = 0; cc < 4; cc++) {
                int c = j*4 + cc;
                int slot = c >> 4, r = c & 15;
                acc1[cc] += xv * sB[slot][r][kk];
                acc3[cc] += xv * sB[2+slot][r][kk];
            }
        }
        __syncthreads();
    }

    if (t >= 0) {
        #pragma unroll
        for (int cc = 0; cc < 4; cc++) {
            int c = j*4 + cc;
            int slot = c >> 4, r = c & 15;
            g_P1[((size_t)t*2 + slot)*RR + r] = acc1[cc];
            g_P3[((size_t)t*2 + slot)*RR + r] = acc3[cc];
        }
    }
}

// ---------------- grouped middle: deltas + SiLU + hbar + P2 + Dlow --------
__global__ void __launch_bounds__(256)
middle_kernel(const float* __restrict__ A1, const float* __restrict__ A3,
              const float* __restrict__ B2, const float* __restrict__ A2)
{
    int key   = blockIdx.y;
    int chunk = blockIdx.x;
    int cnt   = g_cnt[key];
    if (chunk * 32 >= cnt) return;
    int e0 = key >> 3, e1 = key & 7;

    __shared__ int   stok[32];
    __shared__ float scw[32][2];
    __shared__ float sP1[32][2][17];
    __shared__ float sP3[32][2][17];
    __shared__ float sP2[32][2][17];
    __shared__ float sM[6][64*20];

    int tid = threadIdx.x;
    if (tid < 32) {
        int it = chunk * 32 + tid;
        stok[tid] = (it < cnt) ? g_list[key*TT + it] : -1;
    }
    __syncthreads();
    if (tid < 64) {
        int lt = tid >> 1, slot = tid & 1;
        int t = stok[lt];
        scw[lt][slot] = (t >= 0) ? g_cw[t*2 + slot] : 0.0f;
    }
    for (int idx = tid; idx < 1024; idx += 256) {
        int lt = idx >> 5, slot = (idx >> 4) & 1, r = idx & 15;
        int t = stok[lt];
        sP1[lt][slot][r] = (t >= 0) ? g_P1[((size_t)t*2 + slot)*RR + r] : 0.0f;
        sP3[lt][slot][r] = (t >= 0) ? g_P3[((size_t)t*2 + slot)*RR + r] : 0.0f;
    }
    __syncthreads();

    int ltok = tid >> 3;
    int j    = tid & 7;
    int t    = stok[ltok];
    float c0 = scw[ltok][0], c1 = scw[ltok][1];

    float p2a[16], p2b[16];
    #pragma unroll
    for (int r = 0; r < 16; r++) { p2a[r] = 0.0f; p2b[r] = 0.0f; }

    for (int db = 0; db < DD; db += 64) {
        {
            const float* s0 = A1 + ((size_t)e0*DD + db)*RR;
            const float* s1 = A1 + ((size_t)e1*DD + db)*RR;
            const float* s2 = A3 + ((size_t)e0*DD + db)*RR;
            const float* s3 = A3 + ((size_t)e1*DD + db)*RR;
            for (int idx = tid; idx < 1024; idx += 256) {
                int dd = idx >> 4, r = idx & 15;
                int o = dd*20 + r;
                sM[0][o] = s0[idx]; sM[1][o] = s1[idx];
                sM[2][o] = s2[idx]; sM[3][o] = s3[idx];
            }
            const float* b0 = B2 + (size_t)e0*RR*DD + db;
            const float* b1p = B2 + (size_t)e1*RR*DD + db;
            for (int idx = tid; idx < 1024; idx += 256) {
                int r = idx >> 6, dd = idx & 63;
                sM[4][dd*20 + r] = b0[(size_t)r*DD + dd];
                sM[5][dd*20 + r] = b1p[(size_t)r*DD + dd];
            }
        }
        __syncthreads();

        #pragma unroll
        for (int i = 0; i < 8; i++) {
            int dd = j + 8*i;
            int d  = db + dd;
            float u = 0.0f, g = 0.0f;
            if (t >= 0) {
                u = g_U[(size_t)t*DD + d];
                g = g_G[(size_t)t*DD + d];
            }
            const float* a1p = &sM[0][dd*20];
            const float* a1q = &sM[1][dd*20];
            const float* a3p = &sM[2][dd*20];
            const float* a3q = &sM[3][dd*20];

            float d1a = 0.f, d3a = 0.f, d1b = 0.f, d3b = 0.f;
            #pragma unroll
            for (int r = 0; r < 16; r++) {
                d1a += sP1[ltok][0][r] * a1p[r];
                d3a += sP3[ltok][0][r] * a3p[r];
                d1b += sP1[ltok][1][r] * a1q[r];
                d3b += sP3[ltok][1][r] * a3q[r];
            }
            float h1a = u + ALPHA_*d1a, h3a = g + ALPHA_*d3a;
            float h1b = u + ALPHA_*d1b, h3b = g + ALPHA_*d3b;
            float hA = (h1a / (1.0f + __expf(-h1a))) * h3a;
            float hB = (h1b / (1.0f + __expf(-h1b))) * h3b;
            if (t < 0) { hA = 0.0f; hB = 0.0f; }

            if (t >= 0)
                g_H[(size_t)t*DD + d] = c0*hA + c1*hB;

            const float* b2a = &sM[4][dd*20];
            const float* b2b = &sM[5][dd*20];
            #pragma unroll
            for (int r = 0; r < 16; r++) {
                p2a[r] += hA * b2a[r];
                p2b[r] += hB * b2b[r];
            }
        }
        __syncthreads();
    }

    #pragma unroll
    for (int r = 0; r < 16; r++) {
        #pragma unroll
        for (int o = 4; o > 0; o >>= 1) {
            p2a[r] += __shfl_down_sync(0xffffffffu, p2a[r], o);
            p2b[r] += __shfl_down_sync(0xffffffffu, p2b[r], o);
        }
    }
    if (j == 0) {
        #pragma unroll
        for (int r = 0; r < 16; r++) {
            sP2[ltok][0][r] = p2a[r];
            sP2[ltok][1][r] = p2b[r];
        }
    }
    __syncthreads();

    for (int db = 0; db < DD; db += 64) {
        {
            const float* s0 = A2 + ((size_t)e0*DD + db)*RR;
            const float* s1 = A2 + ((size_t)e1*DD + db)*RR;
            for (int idx = tid; idx < 1024; idx += 256) {
                int dd = idx >> 4, r = idx & 15;
                int o = dd*20 + r;
                sM[0][o] = s0[idx];
                sM[1][o] = s1[idx];
            }
        }
        __syncthreads();
        if (t >= 0) {
            #pragma unroll
            for (int i = 0; i < 8; i++) {
                int dd = j + 8*i;
                int d  = db + dd;
                const float* a2p = &sM[0][dd*20];
                const float* a2q = &sM[1][dd*20];
                float s0 = 0.f, s1 = 0.f;
                #pragma unroll
                for (int r = 0; r < 16; r++) {
                    s0 += sP2[ltok][0][r] * a2p[r];
                    s1 += sP2[ltok][1][r] * a2q[r];
                }
                g_DL[(size_t)t*DD + d] = ALPHA_ * (c0*s0 + c1*s1);
            }
        }
        __syncthreads();
    }
}

// ---------------- host launch ---------------------------------------------
extern "C" void kernel_launch(void* const* d_in, const int* in_sizes, int n_in,
                              void* d_out, int out_size)
{
    const float* x     = (const float*)d_in[0];
    const float* Wg    = (const float*)d_in[1];
    const float* Wup   = (const float*)d_in[2];
    const float* Wgate = (const float*)d_in[3];
    const float* Wdown = (const float*)d_in[4];
    const float* A1    = (const float*)d_in[5];
    const float* B1    = (const float*)d_in[6];
    const float* A2    = (const float*)d_in[7];
    const float* B2    = (const float*)d_in[8];
    const float* A3    = (const float*)d_in[9];
    const float* B3    = (const float*)d_in[10];
    float* out = (float*)d_out;

    float *U, *G, *H, *DL;
    cudaGetSymbolAddress((void**)&U,  g_U);
    cudaGetSymbolAddress((void**)&G,  g_G);
    cudaGetSymbolAddress((void**)&H,  g_H);
    cudaGetSymbolAddress((void**)&DL, g_DL);

    zero_cnt_kernel<<<1, 64>>>();
    router_kernel<<<TT/8, 256>>>(x, Wg);

    dim3 ggrid(DD/128, TT/128);
    gemm_bf16x3<0><<<ggrid, 512>>>(x, Wup,   nullptr, U, TT, DD, DD);
    gemm_bf16x3<0><<<ggrid, 512>>>(x, Wgate, nullptr, G, TT, DD, DD);

    lora_in_kernel<<<dim3(256, NKEY), 256>>>(x, B1, B3);
    middle_kernel <<<dim3(256, NKEY), 256>>>(A1, A3, B2, A2);

    gemm_bf16x3<1><<<ggrid, 512>>>(H, Wdown, DL, out, TT, DD, DD);
}

// round 7
// speedup vs baseline: 1.4469x; 1.1652x over previous
#include <cuda_runtime.h>
#include <cuda_bf16.h>
#include <stdint.h>
#include <cstdint>
#include <math.h>

#define TT 8192
#define DD 2048
#define RR 16
#define ALPHA_ 2.0f
#define NKEY 64

// ---------------- scratch (device globals: allocation-free) ----------------
__device__ float g_U [(size_t)TT*DD];
__device__ float g_G [(size_t)TT*DD];
__device__ float g_DL[(size_t)TT*DD];
__device__ float g_P1[(size_t)TT*2*RR];
__device__ float g_P3[(size_t)TT*2*RR];
__device__ float g_cw[TT*2];
__device__ int   g_cnt[NKEY];
__device__ int   g_list[NKEY*TT];

__device__ __nv_bfloat16 g_Xh[(size_t)TT*DD];
__device__ __nv_bfloat16 g_Xl[(size_t)TT*DD];
__device__ __nv_bfloat16 g_Hh[(size_t)TT*DD];
__device__ __nv_bfloat16 g_Hl[(size_t)TT*DD];
__device__ __nv_bfloat16 g_Wuph[(size_t)DD*DD];
__device__ __nv_bfloat16 g_Wupl[(size_t)DD*DD];
__device__ __nv_bfloat16 g_Wgh [(size_t)DD*DD];
__device__ __nv_bfloat16 g_Wgl [(size_t)DD*DD];
__device__ __nv_bfloat16 g_Wdh [(size_t)DD*DD];
__device__ __nv_bfloat16 g_Wdl [(size_t)DD*DD];

// ---------------- zero the bucket counters ---------------------------------
__global__ void zero_cnt_kernel() {
    if (threadIdx.x < NKEY) g_cnt[threadIdx.x] = 0;
}

// ---------------- fp32 -> bf16 hi/lo split ---------------------------------
__global__ void split_kernel(const float* __restrict__ src,
                             __nv_bfloat16* __restrict__ h,
                             __nv_bfloat16* __restrict__ l, int n4)
{
    int i = blockIdx.x * blockDim.x + threadIdx.x;
    int stride = gridDim.x * blockDim.x;
    for (; i < n4; i += stride) {
        float4 v = ((const float4*)src)[i];
        __nv_bfloat16 b0 = __float2bfloat16_rn(v.x);
        __nv_bfloat16 b1 = __float2bfloat16_rn(v.y);
        __nv_bfloat16 b2 = __float2bfloat16_rn(v.z);
        __nv_bfloat16 b3 = __float2bfloat16_rn(v.w);
        __nv_bfloat16 r0 = __float2bfloat16_rn(v.x - __bfloat162float(b0));
        __nv_bfloat16 r1 = __float2bfloat16_rn(v.y - __bfloat162float(b1));
        __nv_bfloat16 r2 = __float2bfloat16_rn(v.z - __bfloat162float(b2));
        __nv_bfloat16 r3 = __float2bfloat16_rn(v.w - __bfloat162float(b3));
        __nv_bfloat162 hp0; hp0.x = b0; hp0.y = b1;
        __nv_bfloat162 hp1; hp1.x = b2; hp1.y = b3;
        __nv_bfloat162 lp0; lp0.x = r0; lp0.y = r1;
        __nv_bfloat162 lp1; lp1.x = r2; lp1.y = r3;
        uint2 hv; hv.x = *(unsigned int*)&hp0; hv.y = *(unsigned int*)&hp1;
        uint2 lv; lv.x = *(unsigned int*)&lp0; lv.y = *(unsigned int*)&lp1;
        ((uint2*)h)[i] = hv;
        ((uint2*)l)[i] = lv;
    }
}

// ---------------- router ----------------------------------------------------
__global__ void router_kernel(const float* __restrict__ x,
                              const float* __restrict__ Wg)
{
    int w    = (blockIdx.x * blockDim.x + threadIdx.x) >> 5;
    int lane = threadIdx.x & 31;
    if (w >= TT) return;
    const float* xr = x + (size_t)w * DD;
    float a0=0.f,a1=0.f,a2=0.f,a3=0.f,a4=0.f,a5=0.f,a6=0.f,a7=0.f;
    for (int k = lane; k < DD; k += 32) {
        float xv = xr[k];
        a0 += xv * Wg[0*DD+k]; a1 += xv * Wg[1*DD+k];
        a2 += xv * Wg[2*DD+k]; a3 += xv * Wg[3*DD+k];
        a4 += xv * Wg[4*DD+k]; a5 += xv * Wg[5*DD+k];
        a6 += xv * Wg[6*DD+k]; a7 += xv * Wg[7*DD+k];
    }
    #pragma unroll
    for (int o = 16; o > 0; o >>= 1) {
        a0 += __shfl_xor_sync(0xffffffffu, a0, o);
        a1 += __shfl_xor_sync(0xffffffffu, a1, o);
        a2 += __shfl_xor_sync(0xffffffffu, a2, o);
        a3 += __shfl_xor_sync(0xffffffffu, a3, o);
        a4 += __shfl_xor_sync(0xffffffffu, a4, o);
        a5 += __shfl_xor_sync(0xffffffffu, a5, o);
        a6 += __shfl_xor_sync(0xffffffffu, a6, o);
        a7 += __shfl_xor_sync(0xffffffffu, a7, o);
    }
    if (lane == 0) {
        float v[8] = {a0,a1,a2,a3,a4,a5,a6,a7};
        int e0 = 0;
        #pragma unroll
        for (int e = 1; e < 8; e++) if (v[e] > v[e0]) e0 = e;
        int e1 = -1; float best = -3.0e38f;
        #pragma unroll
        for (int e = 0; e < 8; e++) if (e != e0 && v[e] > best) { best = v[e]; e1 = e; }
        float ex = __expf(best - v[e0]);
        float c0 = 1.0f / (1.0f + ex);
        float c1 = ex * c0;
        g_cw[w*2+0] = c0;
        g_cw[w*2+1] = c1;
        int key = e0 * 8 + e1;
        int pos = atomicAdd(&g_cnt[key], 1);
        g_list[key*TT + pos] = w;
    }
}

// ---------------- bf16x3 HMMA GEMM v2: pre-split inputs + cp.async --------
// C = A[M,K]*B[N,K]^T (+Csrc); A,B given as bf16 hi/lo pairs.
// 128x128 tile, BK=32 bf16, double-buffered cp.async, pitch-20-word smem
// (layout identical to the round-4 kernel that validated the MMA mapping).
#define MMA16816(dreg, Ra0, Ra1, Ra2, Ra3, Rb0, Rb1)                          \
    asm volatile(                                                             \
        "mma.sync.aligned.m16n8k16.row.col.f32.bf16.bf16.f32 "                \
        "{%0,%1,%2,%3},{%4,%5,%6,%7},{%8,%9},{%0,%1,%2,%3};"                  \
        : "+f"((dreg)[0]), "+f"((dreg)[1]), "+f"((dreg)[2]), "+f"((dreg)[3])  \
        : "r"(Ra0), "r"(Ra1), "r"(Ra2), "r"(Ra3), "r"(Rb0), "r"(Rb1))

#define MAT_W 2560                 // words per matrix slab (128 rows * 20)
#define STG_W (4*MAT_W)            // words per stage
#define SMEM_V2 (2*STG_W*4)        // 81920 bytes

__device__ __forceinline__ uint32_t smem_u32(const void* p) {
    uint32_t a;
    asm("{ .reg .u64 t; cvta.to.shared.u64 t, %1; cvt.u32.u64 %0, t; }" : "=r"(a) : "l"(p));
    return a;
}

__device__ __forceinline__ void issue_v2(
    uint32_t sb, int s, int kt, int tid,
    const __nv_bfloat16* __restrict__ Ah, const __nv_bfloat16* __restrict__ Al,
    const __nv_bfloat16* __restrict__ Bh, const __nv_bfloat16* __restrict__ Bl,
    int bm, int bn)
{
    int row = tid >> 2;
    int c4  = (tid & 3) * 4;                 // word offset within row
    int kb  = kt * 32 + c4 * 2;              // bf16 column
    uint32_t base = sb + (uint32_t)(s * STG_W + row * 20 + c4) * 4;
    const void* p0 = Ah + (size_t)(bm + row) * DD + kb;
    const void* p1 = Al + (size_t)(bm + row) * DD + kb;
    const void* p2 = Bh + (size_t)(bn + row) * DD + kb;
    const void* p3 = Bl + (size_t)(bn + row) * DD + kb;
    asm volatile("cp.async.cg.shared.global [%0], [%1], 16;" :: "r"(base),             "l"(p0) : "memory");
    asm volatile("cp.async.cg.shared.global [%0], [%1], 16;" :: "r"(base + MAT_W*4),   "l"(p1) : "memory");
    asm volatile("cp.async.cg.shared.global [%0], [%1], 16;" :: "r"(base + 2*MAT_W*4), "l"(p2) : "memory");
    asm volatile("cp.async.cg.shared.global [%0], [%1], 16;" :: "r"(base + 3*MAT_W*4), "l"(p3) : "memory");
}

template<int ADD>
__global__ void __launch_bounds__(512)
gemm_v2(const __nv_bfloat16* __restrict__ Ah, const __nv_bfloat16* __restrict__ Al,
        const __nv_bfloat16* __restrict__ Bh, const __nv_bfloat16* __restrict__ Bl,
        const float* __restrict__ Csrc, float* __restrict__ C)
{
    extern __shared__ __align__(16) unsigned int dsm[];
    uint32_t sb = smem_u32(dsm);

    int tid  = threadIdx.x;
    int lane = tid & 31, warp = tid >> 5;
    int g  = lane >> 2, t4 = lane & 3;
    int wm = warp >> 2, wn = warp & 3;
    int bm = blockIdx.y * 128, bn = blockIdx.x * 128;

    float acc[2][4][4];
    #pragma unroll
    for (int i = 0; i < 2; i++)
        #pragma unroll
        for (int j = 0; j < 4; j++)
            #pragma unroll
            for (int q = 0; q < 4; q++) acc[i][j][q] = 0.0f;

    issue_v2(sb, 0, 0, tid, Ah, Al, Bh, Bl, bm, bn);
    asm volatile("cp.async.commit_group;" ::: "memory");

    const int NKT = DD / 32;   // 64
    for (int kt = 0; kt < NKT; kt++) {
        if (kt + 1 < NKT)
            issue_v2(sb, (kt + 1) & 1, kt + 1, tid, Ah, Al, Bh, Bl, bm, bn);
        asm volatile("cp.async.commit_group;" ::: "memory");
        asm volatile("cp.async.wait_group 1;" ::: "memory");
        __syncthreads();

        const unsigned int* S   = dsm + (kt & 1) * STG_W;
        const unsigned int* SAl = S + MAT_W;
        const unsigned int* SBh = S + 2*MAT_W;
        const unsigned int* SBl = S + 3*MAT_W;

        #pragma unroll
        for (int ks = 0; ks < 2; ks++) {
            int kw = ks * 8;
            unsigned int bhf[4][2], blf[4][2], af[2][4];
            #pragma unroll
            for (int nt = 0; nt < 4; nt++) {
                int o = (wn*32 + nt*8 + g) * 20 + kw + t4;
                bhf[nt][0] = SBh[o]; bhf[nt][1] = SBh[o + 4];
                blf[nt][0] = SBl[o]; blf[nt][1] = SBl[o + 4];
            }
            #pragma unroll
            for (int mt = 0; mt < 2; mt++) {
                int o = (wm*32 + mt*16 + g) * 20 + kw + t4;
                af[mt][0] = S[o];       af[mt][1] = S[o + 160];
                af[mt][2] = S[o + 4];   af[mt][3] = S[o + 164];
            }
            #pragma unroll
            for (int mt = 0; mt < 2; mt++)
                #pragma unroll
                for (int nt = 0; nt < 4; nt++)
                    MMA16816(acc[mt][nt], af[mt][0], af[mt][1], af[mt][2], af[mt][3],
                             bhf[nt][0], bhf[nt][1]);
            #pragma unroll
            for (int mt = 0; mt < 2; mt++)
                #pragma unroll
                for (int nt = 0; nt < 4; nt++)
                    MMA16816(acc[mt][nt], af[mt][0], af[mt][1], af[mt][2], af[mt][3],
                             blf[nt][0], blf[nt][1]);
            #pragma unroll
            for (int mt = 0; mt < 2; mt++) {
                int o = (wm*32 + mt*16 + g) * 20 + kw + t4;
                af[mt][0] = SAl[o];     af[mt][1] = SAl[o + 160];
                af[mt][2] = SAl[o + 4]; af[mt][3] = SAl[o + 164];
            }
            #pragma unroll
            for (int mt = 0; mt < 2; mt++)
                #pragma unroll
                for (int nt = 0; nt < 4; nt++)
                    MMA16816(acc[mt][nt], af[mt][0], af[mt][1], af[mt][2], af[mt][3],
                             bhf[nt][0], bhf[nt][1]);
        }
        __syncthreads();
    }

    // epilogue (register -> gmem, same mapping as round 4)
    #pragma unroll
    for (int mt = 0; mt < 2; mt++) {
        int r0 = bm + wm*32 + mt*16 + g;
        #pragma unroll
        for (int nt = 0; nt < 4; nt++) {
            int c0 = bn + wn*32 + nt*8 + t4*2;
            float2 v0 = make_float2(acc[mt][nt][0], acc[mt][nt][1]);
            float2 v1 = make_float2(acc[mt][nt][2], acc[mt][nt][3]);
            if (ADD) {
                float2 s0 = *(const float2*)(Csrc + (size_t)r0 * DD + c0);
                float2 s1 = *(const float2*)(Csrc + (size_t)(r0+8) * DD + c0);
                v0.x += s0.x; v0.y += s0.y;
                v1.x += s1.x; v1.y += s1.y;
            }
            *(float2*)(C + (size_t)r0     * DD + c0) = v0;
            *(float2*)(C + (size_t)(r0+8) * DD + c0) = v1;
        }
    }
}

// ---------------- grouped LoRA-in: P1/P3 = x @ B1[e]^T, x @ B3[e]^T -------
__global__ void __launch_bounds__(256)
lora_in_kernel(const float* __restrict__ x,
               const float* __restrict__ B1, const float* __restrict__ B3)
{
    int key   = blockIdx.y;
    int chunk = blockIdx.x;
    int cnt   = g_cnt[key];
    if (chunk * 32 >= cnt) return;
    int e0 = key >> 3, e1 = key & 7;

    __shared__ int   stok[32];
    __shared__ float sx[32][65];
    __shared__ float sB[4][16][65];

    int tid = threadIdx.x;
    if (tid < 32) {
        int it = chunk * 32 + tid;
        stok[tid] = (it < cnt) ? g_list[key*TT + it] : -1;
    }
    __syncthreads();

    int ltok = tid >> 3;
    int j    = tid & 7;
    int t    = stok[ltok];

    float acc1[4] = {0,0,0,0};
    float acc3[4] = {0,0,0,0};

    for (int kb = 0; kb < DD; kb += 64) {
        {
            int row = tid >> 3, cg = (tid & 7) * 8;
            int tok = stok[row];
            if (tok >= 0) {
                const float* src = x + (size_t)tok * DD + kb + cg;
                float4 v0 = *(const float4*)src;
                float4 v1 = *(const float4*)(src + 4);
                sx[row][cg+0]=v0.x; sx[row][cg+1]=v0.y; sx[row][cg+2]=v0.z; sx[row][cg+3]=v0.w;
                sx[row][cg+4]=v1.x; sx[row][cg+5]=v1.y; sx[row][cg+6]=v1.z; sx[row][cg+7]=v1.w;
            } else {
                #pragma unroll
                for (int q = 0; q < 8; q++) sx[row][cg+q] = 0.0f;
            }
        }
        {
            int s  = tid >> 6;
            int rr = (tid & 63) >> 2;
            int cg = (tid & 3) * 16;
            int e  = (s & 1) ? e1 : e0;
            const float* M = ((s < 2) ? B1 : B3) + ((size_t)e * RR + rr) * DD + kb + cg;
            #pragma unroll
            for (int q = 0; q < 16; q += 4) {
                float4 v = *(const float4*)(M + q);
                sB[s][rr][cg+q+0]=v.x; sB[s][rr][cg+q+1]=v.y;
                sB[s][rr][cg+q+2]=v.z; sB[s][rr][cg+q+3]=v.w;
            }
        }
        __syncthreads();

        #pragma unroll 4
        for (int kk = 0; kk < 64; kk++) {
            float xv = sx[ltok][kk];
            #pragma unroll
            for (int cc = 0; cc < 4; cc++) {
                int c = j*4 + cc;
                int slot = c >> 4, r = c & 15;
                acc1[cc] += xv * sB[slot][r][kk];
                acc3[cc] += xv * sB[2+slot][r][kk];
            }
        }
        __syncthreads();
    }

    if (t >= 0) {
        #pragma unroll
        for (int cc = 0; cc < 4; cc++) {
            int c = j*4 + cc;
            int slot = c >> 4, r = c & 15;
            g_P1[((size_t)t*2 + slot)*RR + r] = acc1[cc];
            g_P3[((size_t)t*2 + slot)*RR + r] = acc3[cc];
        }
    }
}

// ---------------- grouped middle: deltas + SiLU + hbar + P2 + Dlow --------
__global__ void __launch_bounds__(256)
middle_kernel(const float* __restrict__ A1, const float* __restrict__ A3,
              const float* __restrict__ B2, const float* __restrict__ A2)
{
    int key   = blockIdx.y;
    int chunk = blockIdx.x;
    int cnt   = g_cnt[key];
    if (chunk * 32 >= cnt) return;
    int e0 = key >> 3, e1 = key & 7;

    __shared__ int   stok[32];
    __shared__ float scw[32][2];
    __shared__ float sP1[32][2][17];
    __shared__ float sP3[32][2][17];
    __shared__ float sP2[32][2][17];
    __shared__ float sM[6][64*20];

    int tid = threadIdx.x;
    if (tid < 32) {
        int it = chunk * 32 + tid;
        stok[tid] = (it < cnt) ? g_list[key*TT + it] : -1;
    }
    __syncthreads();
    if (tid < 64) {
        int lt = tid >> 1, slot = tid & 1;
        int t = stok[lt];
        scw[lt][slot] = (t >= 0) ? g_cw[t*2 + slot] : 0.0f;
    }
    for (int idx = tid; idx < 1024; idx += 256) {
        int lt = idx >> 5, slot = (idx >> 4) & 1, r = idx & 15;
        int t = stok[lt];
        sP1[lt][slot][r] = (t >= 0) ? g_P1[((size_t)t*2 + slot)*RR + r] : 0.0f;
        sP3[lt][slot][r] = (t >= 0) ? g_P3[((size_t)t*2 + slot)*RR + r] : 0.0f;
    }
    __syncthreads();

    int ltok = tid >> 3;
    int j    = tid & 7;
    int t    = stok[ltok];
    float c0 = scw[ltok][0], c1 = scw[ltok][1];

    float p2a[16], p2b[16];
    #pragma unroll
    for (int r = 0; r < 16; r++) { p2a[r] = 0.0f; p2b[r] = 0.0f; }

    for (int db = 0; db < DD; db += 64) {
        {
            const float* s0 = A1 + ((size_t)e0*DD + db)*RR;
            const float* s1 = A1 + ((size_t)e1*DD + db)*RR;
            const float* s2 = A3 + ((size_t)e0*DD + db)*RR;
            const float* s3 = A3 + ((size_t)e1*DD + db)*RR;
            for (int idx = tid; idx < 1024; idx += 256) {
                int dd = idx >> 4, r = idx & 15;
                int o = dd*20 + r;
                sM[0][o] = s0[idx]; sM[1][o] = s1[idx];
                sM[2][o] = s2[idx]; sM[3][o] = s3[idx];
            }
            const float* b0 = B2 + (size_t)e0*RR*DD + db;
            const float* b1p = B2 + (size_t)e1*RR*DD + db;
            for (int idx = tid; idx < 1024; idx += 256) {
                int r = idx >> 6, dd = idx & 63;
                sM[4][dd*20 + r] = b0[(size_t)r*DD + dd];
                sM[5][dd*20 + r] = b1p[(size_t)r*DD + dd];
            }
        }
        __syncthreads();

        #pragma unroll
        for (int i = 0; i < 8; i++) {
            int dd = j + 8*i;
            int d  = db + dd;
            float u = 0.0f, g = 0.0f;
            if (t >= 0) {
                u = g_U[(size_t)t*DD + d];
                g = g_G[(size_t)t*DD + d];
            }
            const float* a1p = &sM[0][dd*20];
            const float* a1q = &sM[1][dd*20];
            const float* a3p = &sM[2][dd*20];
            const float* a3q = &sM[3][dd*20];

            float d1a = 0.f, d3a = 0.f, d1b = 0.f, d3b = 0.f;
            #pragma unroll
            for (int r = 0; r < 16; r++) {
                d1a += sP1[ltok][0][r] * a1p[r];
                d3a += sP3[ltok][0][r] * a3p[r];
                d1b += sP1[ltok][1][r] * a1q[r];
                d3b += sP3[ltok][1][r] * a3q[r];
            }
            float h1a = u + ALPHA_*d1a, h3a = g + ALPHA_*d3a;
            float h1b = u + ALPHA_*d1b, h3b = g + ALPHA_*d3b;
            float hA = (h1a / (1.0f + __expf(-h1a))) * h3a;
            float hB = (h1b / (1.0f + __expf(-h1b))) * h3b;
            if (t < 0) { hA = 0.0f; hB = 0.0f; }

            if (t >= 0) {
                float hv = c0*hA + c1*hB;
                __nv_bfloat16 hh = __float2bfloat16_rn(hv);
                g_Hh[(size_t)t*DD + d] = hh;
                g_Hl[(size_t)t*DD + d] = __float2bfloat16_rn(hv - __bfloat162float(hh));
            }

            const float* b2a = &sM[4][dd*20];
            const float* b2b = &sM[5][dd*20];
            #pragma unroll
            for (int r = 0; r < 16; r++) {
                p2a[r] += hA * b2a[r];
                p2b[r] += hB * b2b[r];
            }
        }
        __syncthreads();
    }

    #pragma unroll
    for (int r = 0; r < 16; r++) {
        #pragma unroll
        for (int o = 4; o > 0; o >>= 1) {
            p2a[r] += __shfl_down_sync(0xffffffffu, p2a[r], o);
            p2b[r] += __shfl_down_sync(0xffffffffu, p2b[r], o);
        }
    }
    if (j == 0) {
        #pragma unroll
        for (int r = 0; r < 16; r++) {
            sP2[ltok][0][r] = p2a[r];
            sP2[ltok][1][r] = p2b[r];
        }
    }
    __syncthreads();

    for (int db = 0; db < DD; db += 64) {
        {
            const float* s0 = A2 + ((size_t)e0*DD + db)*RR;
            const float* s1 = A2 + ((size_t)e1*DD + db)*RR;
            for (int idx = tid; idx < 1024; idx += 256) {
                int dd = idx >> 4, r = idx & 15;
                int o = dd*20 + r;
                sM[0][o] = s0[idx];
                sM[1][o] = s1[idx];
            }
        }
        __syncthreads();
        if (t >= 0) {
            #pragma unroll
            for (int i = 0; i < 8; i++) {
                int dd = j + 8*i;
                int d  = db + dd;
                const float* a2p = &sM[0][dd*20];
                const float* a2q = &sM[1][dd*20];
                float s0 = 0.f, s1 = 0.f;
                #pragma unroll
                for (int r = 0; r < 16; r++) {
                    s0 += sP2[ltok][0][r] * a2p[r];
                    s1 += sP2[ltok][1][r] * a2q[r];
                }
                g_DL[(size_t)t*DD + d] = ALPHA_ * (c0*s0 + c1*s1);
            }
        }
        __syncthreads();
    }
}

// ---------------- host launch ---------------------------------------------
extern "C" void kernel_launch(void* const* d_in, const int* in_sizes, int n_in,
                              void* d_out, int out_size)
{
    const float* x     = (const float*)d_in[0];
    const float* Wg    = (const float*)d_in[1];
    const float* Wup   = (const float*)d_in[2];
    const float* Wgate = (const float*)d_in[3];
    const float* Wdown = (const float*)d_in[4];
    const float* A1    = (const float*)d_in[5];
    const float* B1    = (const float*)d_in[6];
    const float* A2    = (const float*)d_in[7];
    const float* B2    = (const float*)d_in[8];
    const float* A3    = (const float*)d_in[9];
    const float* B3    = (const float*)d_in[10];
    float* out = (float*)d_out;

    float *U, *G, *DL;
    cudaGetSymbolAddress((void**)&U,  g_U);
    cudaGetSymbolAddress((void**)&G,  g_G);
    cudaGetSymbolAddress((void**)&DL, g_DL);
    __nv_bfloat16 *Xh, *Xl, *Hh, *Hl, *Wuph, *Wupl, *Wgh, *Wgl, *Wdh, *Wdl;
    cudaGetSymbolAddress((void**)&Xh, g_Xh);
    cudaGetSymbolAddress((void**)&Xl, g_Xl);
    cudaGetSymbolAddress((void**)&Hh, g_Hh);
    cudaGetSymbolAddress((void**)&Hl, g_Hl);
    cudaGetSymbolAddress((void**)&Wuph, g_Wuph);
    cudaGetSymbolAddress((void**)&Wupl, g_Wupl);
    cudaGetSymbolAddress((void**)&Wgh,  g_Wgh);
    cudaGetSymbolAddress((void**)&Wgl,  g_Wgl);
    cudaGetSymbolAddress((void**)&Wdh,  g_Wdh);
    cudaGetSymbolAddress((void**)&Wdl,  g_Wdl);

    cudaFuncSetAttribute(gemm_v2<0>, cudaFuncAttributeMaxDynamicSharedMemorySize, SMEM_V2);
    cudaFuncSetAttribute(gemm_v2<1>, cudaFuncAttributeMaxDynamicSharedMemorySize, SMEM_V2);

    zero_cnt_kernel<<<1, 64>>>();
    router_kernel<<<TT/8, 256>>>(x, Wg);

    split_kernel<<<8192, 256>>>(x,     Xh,   Xl,   TT*DD/4);
    split_kernel<<<4096, 256>>>(Wup,   Wuph, Wupl, DD*DD/4);
    split_kernel<<<4096, 256>>>(Wgate, Wgh,  Wgl,  DD*DD/4);
    split_kernel<<<4096, 256>>>(Wdown, Wdh,  Wdl,  DD*DD/4);

    dim3 ggrid(DD/128, TT/128);
    gemm_v2<0><<<ggrid, 512, SMEM_V2>>>(Xh, Xl, Wuph, Wupl, nullptr, U);
    gemm_v2<0><<<ggrid, 512, SMEM_V2>>>(Xh, Xl, Wgh,  Wgl,  nullptr, G);

    lora_in_kernel<<<dim3(256, NKEY), 256>>>(x, B1, B3);
    middle_kernel <<<dim3(256, NKEY), 256>>>(A1, A3, B2, A2);

    gemm_v2<1><<<ggrid, 512, SMEM_V2>>>(Hh, Hl, Wdh, Wdl, DL, out);
}